// round 2
// baseline (speedup 1.0000x reference)
#include <cuda_runtime.h>
#include <cuda_bf16.h>
#include <stdint.h>

#define BATCH 65536
#define VOCAB 1048576

// ---------------- device scratch (no allocation allowed) ----------------
__device__ uint16_t g_bufA_hi[BATCH * 1024];
__device__ uint16_t g_bufA_lo[BATCH * 1024];
__device__ uint16_t g_bufB_hi[BATCH * 1024];
__device__ uint16_t g_bufB_lo[BATCH * 1024];
__device__ uint16_t g_wt_hi[2408448];
__device__ uint16_t g_wt_lo[2408448];

// weight offsets (transposed, K padded):
// bw0 -> [512 ,  32] off 0
// bw1 -> [256 , 512] off 16384
// bw2 -> [128 , 256] off 147456
// tw0 -> [1024, 512] off 180224
// tw1 -> [1024,1024] off 704512
// tw2 -> [512 ,1024] off 1753088
// tw3 -> [256 , 512] off 2277376     total 2408448

__device__ __forceinline__ void f2hilo(float x, uint16_t &hi, uint16_t &lo) {
    __nv_bfloat16 h = __float2bfloat16(x);
    float hf = __bfloat162float(h);
    __nv_bfloat16 l = __float2bfloat16(x - hf);
    hi = __bfloat16_as_ushort(h);
    lo = __bfloat16_as_ushort(l);
}

__device__ __forceinline__ float b2f(uint16_t u) {
    return __bfloat162float(__ushort_as_bfloat16(u));
}

// ---------------- conversion kernels ----------------
__global__ void conv_dense_kernel(const float* __restrict__ d,
                                  uint16_t* __restrict__ hi, uint16_t* __restrict__ lo) {
    int idx = blockIdx.x * blockDim.x + threadIdx.x;   // BATCH*32
    int b = idx >> 5, k = idx & 31;
    float v = (k < 13) ? d[b * 13 + k] : 0.f;
    uint16_t h, l;
    f2hilo(v, h, l);
    hi[idx] = h; lo[idx] = l;
}

__global__ void conv_wt_kernel(const float* __restrict__ W,
                               uint16_t* __restrict__ hi, uint16_t* __restrict__ lo,
                               int K, int N, int Kpad) {
    int idx = blockIdx.x * blockDim.x + threadIdx.x;
    if (idx >= N * Kpad) return;
    int n = idx / Kpad, k = idx % Kpad;
    float v = (k < K) ? W[(size_t)k * N + n] : 0.f;
    uint16_t h, l;
    f2hilo(v, h, l);
    hi[idx] = h; lo[idx] = l;
}

// ---------------- mma helpers ----------------
__device__ __forceinline__ void mma_bf16(float* c, const uint32_t* a, const uint32_t* b) {
    asm volatile(
        "mma.sync.aligned.m16n8k16.row.col.f32.bf16.bf16.f32 "
        "{%0,%1,%2,%3}, {%4,%5,%6,%7}, {%8,%9}, {%0,%1,%2,%3};\n"
        : "+f"(c[0]), "+f"(c[1]), "+f"(c[2]), "+f"(c[3])
        : "r"(a[0]), "r"(a[1]), "r"(a[2]), "r"(a[3]), "r"(b[0]), "r"(b[1]));
}

__device__ __forceinline__ void ldsm4(uint32_t* r, const uint16_t* p) {
    uint32_t addr = (uint32_t)__cvta_generic_to_shared(p);
    asm volatile("ldmatrix.sync.aligned.m8n8.x4.shared.b16 {%0,%1,%2,%3}, [%4];\n"
                 : "=r"(r[0]), "=r"(r[1]), "=r"(r[2]), "=r"(r[3])
                 : "r"(addr));
}

// ---------------- generic bf16x3 GEMM: out = act(A @ W^T + bias) ----------------
// A: [M=BATCH, K] row-major hi/lo.  W: [N, K] row-major (pre-transposed) hi/lo.
// Block tile 128x128, BK=32, 8 warps (4m x 2n), warp tile 32x64.
#define SPAD 40   // smem row stride (bf16) for 32-wide K tile, conflict-free LDSM

__global__ __launch_bounds__(256, 1)
void gemm_bf16x3(const uint16_t* __restrict__ Ahi, const uint16_t* __restrict__ Alo,
                 const uint16_t* __restrict__ Whi, const uint16_t* __restrict__ Wlo,
                 const float* __restrict__ bias,
                 uint16_t* __restrict__ Ohi, uint16_t* __restrict__ Olo,
                 int N, int K, int relu) {
    __shared__ uint16_t sAhi[128 * SPAD], sAlo[128 * SPAD];
    __shared__ uint16_t sBhi[128 * SPAD], sBlo[128 * SPAD];

    const int tid  = threadIdx.x;
    const int lane = tid & 31;
    const int warp = tid >> 5;
    const int wm = warp & 3;          // 0..3  (m groups of 32)
    const int wn = warp >> 2;         // 0..1  (n groups of 64)
    const size_t mBase = (size_t)blockIdx.y * 128;
    const int    nBase = blockIdx.x * 128;

    const int row = tid >> 2;         // 0..63
    const int seg = (tid & 3) * 8;    // 0,8,16,24

    uint4 pAh[2], pAl[2], pBh[2], pBl[2];

    auto gload = [&](int k0) {
        size_t a0 = (mBase + row) * (size_t)K + k0 + seg;
        size_t a1 = (mBase + row + 64) * (size_t)K + k0 + seg;
        pAh[0] = *(const uint4*)(Ahi + a0);
        pAh[1] = *(const uint4*)(Ahi + a1);
        pAl[0] = *(const uint4*)(Alo + a0);
        pAl[1] = *(const uint4*)(Alo + a1);
        size_t b0 = (size_t)(nBase + row) * K + k0 + seg;
        size_t b1 = (size_t)(nBase + row + 64) * K + k0 + seg;
        pBh[0] = *(const uint4*)(Whi + b0);
        pBh[1] = *(const uint4*)(Whi + b1);
        pBl[0] = *(const uint4*)(Wlo + b0);
        pBl[1] = *(const uint4*)(Wlo + b1);
    };
    auto sstore = [&]() {
        *(uint4*)&sAhi[row * SPAD + seg]        = pAh[0];
        *(uint4*)&sAhi[(row + 64) * SPAD + seg] = pAh[1];
        *(uint4*)&sAlo[row * SPAD + seg]        = pAl[0];
        *(uint4*)&sAlo[(row + 64) * SPAD + seg] = pAl[1];
        *(uint4*)&sBhi[row * SPAD + seg]        = pBh[0];
        *(uint4*)&sBhi[(row + 64) * SPAD + seg] = pBh[1];
        *(uint4*)&sBlo[row * SPAD + seg]        = pBl[0];
        *(uint4*)&sBlo[(row + 64) * SPAD + seg] = pBl[1];
    };

    float acc[2][8][4];
#pragma unroll
    for (int a = 0; a < 2; a++)
#pragma unroll
        for (int b = 0; b < 8; b++)
#pragma unroll
            for (int c = 0; c < 4; c++) acc[a][b][c] = 0.f;

    gload(0);
    for (int k0 = 0; k0 < K; k0 += 32) {
        __syncthreads();
        sstore();
        __syncthreads();
        if (k0 + 32 < K) gload(k0 + 32);

#pragma unroll
        for (int kk = 0; kk < 2; kk++) {
            uint32_t aH[2][4], aL[2][4];
#pragma unroll
            for (int mt = 0; mt < 2; mt++) {
                int r = wm * 32 + mt * 16 + (lane & 15);
                int c = kk * 16 + (lane >> 4) * 8;
                ldsm4(aH[mt], &sAhi[r * SPAD + c]);
                ldsm4(aL[mt], &sAlo[r * SPAD + c]);
            }
            uint32_t bH[8][2], bL[8][2];
#pragma unroll
            for (int np = 0; np < 4; np++) {
                int r = wn * 64 + np * 16 + (lane & 7) + ((lane >> 4) << 3);
                int c = kk * 16 + (((lane >> 3) & 1) << 3);
                uint32_t t[4];
                ldsm4(t, &sBhi[r * SPAD + c]);
                bH[np * 2][0] = t[0]; bH[np * 2][1] = t[1];
                bH[np * 2 + 1][0] = t[2]; bH[np * 2 + 1][1] = t[3];
                ldsm4(t, &sBlo[r * SPAD + c]);
                bL[np * 2][0] = t[0]; bL[np * 2][1] = t[1];
                bL[np * 2 + 1][0] = t[2]; bL[np * 2 + 1][1] = t[3];
            }
#pragma unroll
            for (int mt = 0; mt < 2; mt++)
#pragma unroll
                for (int nt = 0; nt < 8; nt++) {
                    mma_bf16(acc[mt][nt], aH[mt], bH[nt]);
                    mma_bf16(acc[mt][nt], aL[mt], bH[nt]);
                    mma_bf16(acc[mt][nt], aH[mt], bL[nt]);
                }
        }
    }

    // epilogue: bias + relu + hi/lo split + store
#pragma unroll
    for (int mt = 0; mt < 2; mt++) {
        size_t m0 = mBase + wm * 32 + mt * 16 + (lane >> 2);
#pragma unroll
        for (int nt = 0; nt < 8; nt++) {
            int n = nBase + wn * 64 + nt * 8 + (lane & 3) * 2;
            float b0 = bias[n], b1 = bias[n + 1];
            float v0 = acc[mt][nt][0] + b0;
            float v1 = acc[mt][nt][1] + b1;
            float v2 = acc[mt][nt][2] + b0;
            float v3 = acc[mt][nt][3] + b1;
            if (relu) {
                v0 = fmaxf(v0, 0.f); v1 = fmaxf(v1, 0.f);
                v2 = fmaxf(v2, 0.f); v3 = fmaxf(v3, 0.f);
            }
            uint16_t h0, l0, h1, l1;
            f2hilo(v0, h0, l0); f2hilo(v1, h1, l1);
            *(uint32_t*)&Ohi[m0 * N + n] = (uint32_t)h0 | ((uint32_t)h1 << 16);
            *(uint32_t*)&Olo[m0 * N + n] = (uint32_t)l0 | ((uint32_t)l1 << 16);
            f2hilo(v2, h0, l0); f2hilo(v3, h1, l1);
            *(uint32_t*)&Ohi[(m0 + 8) * N + n] = (uint32_t)h0 | ((uint32_t)h1 << 16);
            *(uint32_t*)&Olo[(m0 + 8) * N + n] = (uint32_t)l0 | ((uint32_t)l1 << 16);
        }
    }
}

// ---------------- embedding gather + pairwise interaction ----------------
// One warp per sample, 8 samples per block. smem layout per sample: [k=128][v=28] fp32.
__global__ __launch_bounds__(256, 1)
void interact_kernel(const uint16_t* __restrict__ Hhi, const uint16_t* __restrict__ Hlo,
                     const float* __restrict__ emb, const int* __restrict__ sidx,
                     uint16_t* __restrict__ Ohi, uint16_t* __restrict__ Olo) {
    extern __shared__ float comb[];                 // 8 * 128 * 28 floats
    const int warp = threadIdx.x >> 5;
    const int lane = threadIdx.x & 31;
    const size_t s = (size_t)blockIdx.x * 8 + warp;
    float* C = comb + warp * (128 * 28);

    // load h (reconstruct fp32 from hi+lo); also copy to output cols [0,128)
    {
        uint2 hh = *(const uint2*)&Hhi[s * 128 + lane * 4];
        uint2 ll = *(const uint2*)&Hlo[s * 128 + lane * 4];
        uint16_t hu[4] = {(uint16_t)(hh.x & 0xFFFF), (uint16_t)(hh.x >> 16),
                          (uint16_t)(hh.y & 0xFFFF), (uint16_t)(hh.y >> 16)};
        uint16_t lu[4] = {(uint16_t)(ll.x & 0xFFFF), (uint16_t)(ll.x >> 16),
                          (uint16_t)(ll.y & 0xFFFF), (uint16_t)(ll.y >> 16)};
#pragma unroll
        for (int j = 0; j < 4; j++) {
            float v = b2f(hu[j]) + b2f(lu[j]);
            C[(4 * lane + j) * 28 + 0] = v;
            C[(4 * lane + j) * 28 + 27] = 0.f;       // pad vector 27
        }
        *(uint2*)&Ohi[s * 512 + lane * 4] = hh;
        *(uint2*)&Olo[s * 512 + lane * 4] = ll;
    }

    // gather 26 embedding rows
    for (int v = 0; v < 26; v++) {
        int id = sidx[s * 26 + v] & (VOCAB - 1);
        float4 e = *(const float4*)&emb[(size_t)id * 128 + lane * 4];
        C[(4 * lane + 0) * 28 + (v + 1)] = e.x;
        C[(4 * lane + 1) * 28 + (v + 1)] = e.y;
        C[(4 * lane + 2) * 28 + (v + 1)] = e.z;
        C[(4 * lane + 3) * 28 + (v + 1)] = e.w;
    }
    __syncwarp();

    if (lane < 28) {
        // map lane -> upper-triangular 4x4 tile (ti <= tj), 7x7 tile grid
        int rem = lane, ti = 0;
        while (rem >= 7 - ti) { rem -= 7 - ti; ti++; }
        int tj = ti + rem;

        float a4[16];
#pragma unroll
        for (int i = 0; i < 16; i++) a4[i] = 0.f;

        const float* Ca = C + 4 * ti;
        const float* Cb = C + 4 * tj;
#pragma unroll 4
        for (int k = 0; k < 128; k++) {
            float4 av = *(const float4*)(Ca + k * 28);
            float4 bv = *(const float4*)(Cb + k * 28);
            float aa[4] = {av.x, av.y, av.z, av.w};
            float bb[4] = {bv.x, bv.y, bv.z, bv.w};
#pragma unroll
            for (int i = 0; i < 4; i++)
#pragma unroll
                for (int j = 0; j < 4; j++) a4[i * 4 + j] += aa[i] * bb[j];
        }
#pragma unroll
        for (int ai = 0; ai < 4; ai++)
#pragma unroll
            for (int bi = 0; bi < 4; bi++) {
                int i = 4 * ti + ai, j = 4 * tj + bi;
                if (i <= j && j < 27) {
                    int flat = 27 * i - (i * (i - 1)) / 2 + (j - i);
                    uint16_t h, l;
                    f2hilo(a4[ai * 4 + bi], h, l);
                    Ohi[s * 512 + 128 + flat] = h;
                    Olo[s * 512 + 128 + flat] = l;
                }
            }
    } else if (lane == 28) {
        for (int c = 506; c < 512; c++) { Ohi[s * 512 + c] = 0; Olo[s * 512 + c] = 0; }
    }
}

// ---------------- final 256 -> 1 dot ----------------
__global__ void final_dot_kernel(const uint16_t* __restrict__ Ahi, const uint16_t* __restrict__ Alo,
                                 const float* __restrict__ w, const float* __restrict__ b,
                                 float* __restrict__ out) {
    const int warp = threadIdx.x >> 5;
    const int lane = threadIdx.x & 31;
    const size_t s = (size_t)blockIdx.x * 8 + warp;
    uint4 h4 = *(const uint4*)&Ahi[s * 256 + lane * 8];
    uint4 l4 = *(const uint4*)&Alo[s * 256 + lane * 8];
    uint32_t hw[4] = {h4.x, h4.y, h4.z, h4.w};
    uint32_t lw[4] = {l4.x, l4.y, l4.z, l4.w};
    float acc = 0.f;
#pragma unroll
    for (int q = 0; q < 4; q++) {
        float v0 = b2f((uint16_t)(hw[q] & 0xFFFF)) + b2f((uint16_t)(lw[q] & 0xFFFF));
        float v1 = b2f((uint16_t)(hw[q] >> 16))    + b2f((uint16_t)(lw[q] >> 16));
        acc += v0 * w[lane * 8 + q * 2];
        acc += v1 * w[lane * 8 + q * 2 + 1];
    }
#pragma unroll
    for (int o = 16; o; o >>= 1) acc += __shfl_xor_sync(0xFFFFFFFFu, acc, o);
    if (lane == 0) out[s] = acc + b[0];
}

// ---------------- host launch ----------------
extern "C" void kernel_launch(void* const* d_in, const int* in_sizes, int n_in,
                              void* d_out, int out_size) {
    const float* dense = (const float*)d_in[0];
    const int*   sidx  = (const int*)d_in[1];
    const float* emb   = (const float*)d_in[2];
    const float* bw0 = (const float*)d_in[3];  const float* bb0 = (const float*)d_in[4];
    const float* bw1 = (const float*)d_in[5];  const float* bb1 = (const float*)d_in[6];
    const float* bw2 = (const float*)d_in[7];  const float* bb2 = (const float*)d_in[8];
    const float* tw0 = (const float*)d_in[9];  const float* tb0 = (const float*)d_in[10];
    const float* tw1 = (const float*)d_in[11]; const float* tb1 = (const float*)d_in[12];
    const float* tw2 = (const float*)d_in[13]; const float* tb2 = (const float*)d_in[14];
    const float* tw3 = (const float*)d_in[15]; const float* tb3 = (const float*)d_in[16];
    const float* tw4 = (const float*)d_in[17]; const float* tb4 = (const float*)d_in[18];

    uint16_t *bufAh, *bufAl, *bufBh, *bufBl, *wth, *wtl;
    cudaGetSymbolAddress((void**)&bufAh, g_bufA_hi);
    cudaGetSymbolAddress((void**)&bufAl, g_bufA_lo);
    cudaGetSymbolAddress((void**)&bufBh, g_bufB_hi);
    cudaGetSymbolAddress((void**)&bufBl, g_bufB_lo);
    cudaGetSymbolAddress((void**)&wth, g_wt_hi);
    cudaGetSymbolAddress((void**)&wtl, g_wt_lo);

    cudaFuncSetAttribute(interact_kernel, cudaFuncAttributeMaxDynamicSharedMemorySize, 114688);

    dim3 blk(256);

    // input / weight conversion (hi/lo split, weights transposed + K-padded)
    conv_dense_kernel<<<BATCH * 32 / 256, blk>>>(dense, bufAh, bufAl);
    conv_wt_kernel<<<(512 * 32 + 255) / 256, blk>>>(bw0, wth + 0,       wtl + 0,       13,   512, 32);
    conv_wt_kernel<<<(256 * 512 + 255) / 256, blk>>>(bw1, wth + 16384,  wtl + 16384,   512,  256, 512);
    conv_wt_kernel<<<(128 * 256 + 255) / 256, blk>>>(bw2, wth + 147456, wtl + 147456,  256,  128, 256);
    conv_wt_kernel<<<(1024 * 512 + 255) / 256, blk>>>(tw0, wth + 180224, wtl + 180224, 506, 1024, 512);
    conv_wt_kernel<<<(1024 * 1024 + 255) / 256, blk>>>(tw1, wth + 704512, wtl + 704512, 1024, 1024, 1024);
    conv_wt_kernel<<<(512 * 1024 + 255) / 256, blk>>>(tw2, wth + 1753088, wtl + 1753088, 1024, 512, 1024);
    conv_wt_kernel<<<(256 * 512 + 255) / 256, blk>>>(tw3, wth + 2277376, wtl + 2277376, 512, 256, 512);

    // bottom MLP
    gemm_bf16x3<<<dim3(4, 512), blk>>>(bufAh, bufAl, wth + 0,      wtl + 0,      bb0, bufBh, bufBl, 512, 32, 1);
    gemm_bf16x3<<<dim3(2, 512), blk>>>(bufBh, bufBl, wth + 16384,  wtl + 16384,  bb1, bufAh, bufAl, 256, 512, 1);
    gemm_bf16x3<<<dim3(1, 512), blk>>>(bufAh, bufAl, wth + 147456, wtl + 147456, bb2, bufBh, bufBl, 128, 256, 1);

    // gather + interaction -> top input [B, 512] (506 used, 6 zero-padded)
    interact_kernel<<<BATCH / 8, blk, 114688>>>(bufBh, bufBl, emb, sidx, bufAh, bufAl);

    // top MLP
    gemm_bf16x3<<<dim3(8, 512), blk>>>(bufAh, bufAl, wth + 180224,  wtl + 180224,  tb0, bufBh, bufBl, 1024, 512, 1);
    gemm_bf16x3<<<dim3(8, 512), blk>>>(bufBh, bufBl, wth + 704512,  wtl + 704512,  tb1, bufAh, bufAl, 1024, 1024, 1);
    gemm_bf16x3<<<dim3(4, 512), blk>>>(bufAh, bufAl, wth + 1753088, wtl + 1753088, tb2, bufBh, bufBl, 512, 1024, 1);
    gemm_bf16x3<<<dim3(2, 512), blk>>>(bufBh, bufBl, wth + 2277376, wtl + 2277376, tb3, bufAh, bufAl, 256, 512, 1);

    // final 256 -> 1
    final_dot_kernel<<<BATCH / 8, blk>>>(bufAh, bufAl, tw4, tb4, (float*)d_out);
}

// round 4
// speedup vs baseline: 1.1934x; 1.1934x over previous
#include <cuda_runtime.h>
#include <cuda_bf16.h>
#include <stdint.h>

#define BATCH 65536
#define VOCAB 1048576

// ---------------- device scratch (no allocation allowed) ----------------
__device__ uint16_t g_bufA_hi[BATCH * 1024];
__device__ uint16_t g_bufA_lo[BATCH * 1024];
__device__ uint16_t g_bufB_hi[BATCH * 1024];
__device__ uint16_t g_bufB_lo[BATCH * 1024];
__device__ uint16_t g_wt_hi[2408448];
__device__ uint16_t g_wt_lo[2408448];

// weight offsets (transposed [N,K], K padded to mult of 32):
// bw0 -> [512 ,  32] off 0
// bw1 -> [256 , 512] off 16384
// bw2 -> [128 , 256] off 147456
// tw0 -> [1024, 512] off 180224
// tw1 -> [1024,1024] off 704512
// tw2 -> [512 ,1024] off 1753088
// tw3 -> [256 , 512] off 2277376     total 2408448

__device__ __forceinline__ void f2hilo(float x, uint16_t &hi, uint16_t &lo) {
    __nv_bfloat16 h = __float2bfloat16(x);
    float hf = __bfloat162float(h);
    __nv_bfloat16 l = __float2bfloat16(x - hf);
    hi = __bfloat16_as_ushort(h);
    lo = __bfloat16_as_ushort(l);
}
__device__ __forceinline__ float b2f(uint16_t u) {
    return __bfloat162float(__ushort_as_bfloat16(u));
}

// ---------------- PTX helpers ----------------
__device__ __forceinline__ uint32_t smem_u32(const void* p) {
    return (uint32_t)__cvta_generic_to_shared(p);
}
__device__ __forceinline__ void cp16(uint32_t s, const void* g) {
    asm volatile("cp.async.cg.shared.global [%0], [%1], 16;\n" :: "r"(s), "l"(g));
}
#define CP_COMMIT() asm volatile("cp.async.commit_group;\n" ::: "memory")
#define CP_WAIT2()  asm volatile("cp.async.wait_group 2;\n" ::: "memory")

__device__ __forceinline__ void mma_bf16(float* c, const uint32_t* a, const uint32_t* b) {
    asm volatile(
        "mma.sync.aligned.m16n8k16.row.col.f32.bf16.bf16.f32 "
        "{%0,%1,%2,%3}, {%4,%5,%6,%7}, {%8,%9}, {%0,%1,%2,%3};\n"
        : "+f"(c[0]), "+f"(c[1]), "+f"(c[2]), "+f"(c[3])
        : "r"(a[0]), "r"(a[1]), "r"(a[2]), "r"(a[3]), "r"(b[0]), "r"(b[1]));
}
__device__ __forceinline__ void ldsm4(uint32_t* r, uint32_t addr) {
    asm volatile("ldmatrix.sync.aligned.m8n8.x4.shared.b16 {%0,%1,%2,%3}, [%4];\n"
                 : "=r"(r[0]), "=r"(r[1]), "=r"(r[2]), "=r"(r[3])
                 : "r"(addr));
}
// SW64 swizzle for 64-byte rows (conflict-free ldmatrix, 16B-aligned cp.async)
__device__ __forceinline__ uint32_t swz(uint32_t off) {
    return off ^ ((off >> 3) & 0x30);
}

// ---------------- conversion kernels ----------------
__global__ void conv_dense_kernel(const float* __restrict__ d,
                                  uint16_t* __restrict__ hi, uint16_t* __restrict__ lo) {
    int idx = blockIdx.x * blockDim.x + threadIdx.x;   // BATCH*32
    int b = idx >> 5, k = idx & 31;
    float v = (k < 13) ? d[b * 13 + k] : 0.f;
    uint16_t h, l;
    f2hilo(v, h, l);
    hi[idx] = h; lo[idx] = l;
}

__global__ void conv_wt_kernel(const float* __restrict__ W,
                               uint16_t* __restrict__ hi, uint16_t* __restrict__ lo,
                               int K, int N, int Kpad) {
    int idx = blockIdx.x * blockDim.x + threadIdx.x;
    if (idx >= N * Kpad) return;
    int n = idx / Kpad, k = idx % Kpad;
    float v = (k < K) ? W[(size_t)k * N + n] : 0.f;
    uint16_t h, l;
    f2hilo(v, h, l);
    hi[idx] = h; lo[idx] = l;
}

// ---------------- bf16x3 GEMM (HMMA, cp.async 3-stage): O = act(A @ W^T + b) ----
// A: [BATCH, K] hi/lo row-major. W: [N, K] hi/lo row-major.
// Block tile 128x128, BK=32, 8 warps (4m x 2n), warp tile 32x64. 2 CTAs/SM.
#define STAGE_B 32768          // Ah 8K | Al 8K | Bh 8K | Bl 8K
#define OFF_AL  8192
#define OFF_BH  16384
#define OFF_BL  24576

__global__ __launch_bounds__(256, 2)
void gemm_hmma(const uint16_t* __restrict__ Ahi, const uint16_t* __restrict__ Alo,
               const uint16_t* __restrict__ Whi, const uint16_t* __restrict__ Wlo,
               const float* __restrict__ bias,
               uint16_t* __restrict__ Ohi, uint16_t* __restrict__ Olo,
               int Nsz, int K, int relu) {
    extern __shared__ __align__(16) uint8_t dsm[];
    const uint32_t sbase = smem_u32(dsm);

    const int tid  = threadIdx.x;
    const int lane = tid & 31;
    const int warp = tid >> 5;
    const int wm = warp & 3;
    const int wn = warp >> 2;
    const size_t mBase = (size_t)blockIdx.y * 128;
    const int    nBase = blockIdx.x * 128;
    const int    nch   = K >> 5;

    // each thread issues 8 cp.async per chunk: 4 A-half, 4 B-half
    // i in [0,2048): half=i>>10, buf=(i>>9)&1, r=(i>>2)&127, ch=i&3
    auto issue = [&](int c) {
        const uint32_t st = sbase + (c % 3) * STAGE_B;
        const int k0 = c << 5;
#pragma unroll
        for (int q = 0; q < 8; q++) {
            int i = q * 256 + tid;
            int half = i >> 10, buf = (i >> 9) & 1, r = (i >> 2) & 127, ch = i & 3;
            const uint16_t* g;
            uint32_t s;
            if (half == 0) {
                g = (buf ? Alo : Ahi) + (mBase + r) * (size_t)K + k0 + ch * 8;
                s = st + buf * OFF_AL + swz(r * 64 + ch * 16);
            } else {
                g = (buf ? Wlo : Whi) + (size_t)(nBase + r) * K + k0 + ch * 8;
                s = st + OFF_BH + buf * 8192 + swz(r * 64 + ch * 16);
            }
            cp16(s, g);
        }
    };

    float acc[2][8][4];
#pragma unroll
    for (int a = 0; a < 2; a++)
#pragma unroll
        for (int b = 0; b < 8; b++)
#pragma unroll
            for (int c = 0; c < 4; c++) acc[a][b][c] = 0.f;

    issue(0); CP_COMMIT();
    if (nch > 1) issue(1);
    CP_COMMIT();

    for (int c = 0; c < nch; c++) {
        __syncthreads();                 // all warps done with chunk c-1
        if (c + 2 < nch) issue(c + 2);
        CP_COMMIT();
        CP_WAIT2();                      // chunk c landed (for this thread)
        __syncthreads();                 // ...for all threads

        const uint32_t st = sbase + (c % 3) * STAGE_B;
#pragma unroll
        for (int kk = 0; kk < 2; kk++) {
            // A fragments: 32 rows x k16, hi+lo
            uint32_t aH[2][4], aL[2][4];
#pragma unroll
            for (int mt = 0; mt < 2; mt++) {
                uint32_t off = (uint32_t)(wm * 32 + mt * 16 + (lane & 15)) * 64
                             + kk * 32 + (lane >> 4) * 16;
                ldsm4(aH[mt], st + swz(off));
                ldsm4(aL[mt], st + OFF_AL + swz(off));
            }
#pragma unroll
            for (int np = 0; np < 4; np++) {
                uint32_t off = (uint32_t)(wn * 64 + np * 16 + (lane & 7) + ((lane >> 4) << 3)) * 64
                             + kk * 32 + (((lane >> 3) & 1) << 4);
                uint32_t bt[4];
                ldsm4(bt, st + OFF_BH + swz(off));      // B hi
#pragma unroll
                for (int mt = 0; mt < 2; mt++) {
                    mma_bf16(acc[mt][np * 2],     aH[mt], bt);
                    mma_bf16(acc[mt][np * 2 + 1], aH[mt], bt + 2);
                    mma_bf16(acc[mt][np * 2],     aL[mt], bt);
                    mma_bf16(acc[mt][np * 2 + 1], aL[mt], bt + 2);
                }
                ldsm4(bt, st + OFF_BL + swz(off));      // B lo
#pragma unroll
                for (int mt = 0; mt < 2; mt++) {
                    mma_bf16(acc[mt][np * 2],     aH[mt], bt);
                    mma_bf16(acc[mt][np * 2 + 1], aH[mt], bt + 2);
                }
            }
        }
    }

    // epilogue: bias + relu + hi/lo split + store
#pragma unroll
    for (int mt = 0; mt < 2; mt++) {
        size_t m0 = mBase + wm * 32 + mt * 16 + (lane >> 2);
#pragma unroll
        for (int nt = 0; nt < 8; nt++) {
            int n = nBase + wn * 64 + nt * 8 + (lane & 3) * 2;
            float b0 = bias[n], b1 = bias[n + 1];
            float v0 = acc[mt][nt][0] + b0;
            float v1 = acc[mt][nt][1] + b1;
            float v2 = acc[mt][nt][2] + b0;
            float v3 = acc[mt][nt][3] + b1;
            if (relu) {
                v0 = fmaxf(v0, 0.f); v1 = fmaxf(v1, 0.f);
                v2 = fmaxf(v2, 0.f); v3 = fmaxf(v3, 0.f);
            }
            uint16_t h0, l0, h1, l1;
            f2hilo(v0, h0, l0); f2hilo(v1, h1, l1);
            *(uint32_t*)&Ohi[m0 * Nsz + n] = (uint32_t)h0 | ((uint32_t)h1 << 16);
            *(uint32_t*)&Olo[m0 * Nsz + n] = (uint32_t)l0 | ((uint32_t)l1 << 16);
            f2hilo(v2, h0, l0); f2hilo(v3, h1, l1);
            *(uint32_t*)&Ohi[(m0 + 8) * Nsz + n] = (uint32_t)h0 | ((uint32_t)h1 << 16);
            *(uint32_t*)&Olo[(m0 + 8) * Nsz + n] = (uint32_t)l0 | ((uint32_t)l1 << 16);
        }
    }
}

// ---------------- embedding gather + pairwise interaction ----------------
__global__ __launch_bounds__(256, 1)
void interact_kernel(const uint16_t* __restrict__ Hhi, const uint16_t* __restrict__ Hlo,
                     const float* __restrict__ emb, const int* __restrict__ sidx,
                     uint16_t* __restrict__ Ohi, uint16_t* __restrict__ Olo) {
    extern __shared__ float comb[];                 // 8 * 128 * 28 floats
    const int warp = threadIdx.x >> 5;
    const int lane = threadIdx.x & 31;
    const size_t s = (size_t)blockIdx.x * 8 + warp;
    float* C = comb + warp * (128 * 28);

    {
        uint2 hh = *(const uint2*)&Hhi[s * 128 + lane * 4];
        uint2 ll = *(const uint2*)&Hlo[s * 128 + lane * 4];
        uint16_t hu[4] = {(uint16_t)(hh.x & 0xFFFF), (uint16_t)(hh.x >> 16),
                          (uint16_t)(hh.y & 0xFFFF), (uint16_t)(hh.y >> 16)};
        uint16_t lu[4] = {(uint16_t)(ll.x & 0xFFFF), (uint16_t)(ll.x >> 16),
                          (uint16_t)(ll.y & 0xFFFF), (uint16_t)(ll.y >> 16)};
#pragma unroll
        for (int j = 0; j < 4; j++) {
            float v = b2f(hu[j]) + b2f(lu[j]);
            C[(4 * lane + j) * 28 + 0] = v;
            C[(4 * lane + j) * 28 + 27] = 0.f;
        }
        *(uint2*)&Ohi[s * 512 + lane * 4] = hh;
        *(uint2*)&Olo[s * 512 + lane * 4] = ll;
    }

    for (int v = 0; v < 26; v++) {
        int id = sidx[s * 26 + v] & (VOCAB - 1);
        float4 e = *(const float4*)&emb[(size_t)id * 128 + lane * 4];
        C[(4 * lane + 0) * 28 + (v + 1)] = e.x;
        C[(4 * lane + 1) * 28 + (v + 1)] = e.y;
        C[(4 * lane + 2) * 28 + (v + 1)] = e.z;
        C[(4 * lane + 3) * 28 + (v + 1)] = e.w;
    }
    __syncwarp();

    if (lane < 28) {
        int rem = lane, ti = 0;
        while (rem >= 7 - ti) { rem -= 7 - ti; ti++; }
        int tj = ti + rem;

        float a4[16];
#pragma unroll
        for (int i = 0; i < 16; i++) a4[i] = 0.f;

        const float* Ca = C + 4 * ti;
        const float* Cb = C + 4 * tj;
#pragma unroll 4
        for (int k = 0; k < 128; k++) {
            float4 av = *(const float4*)(Ca + k * 28);
            float4 bv = *(const float4*)(Cb + k * 28);
            float aa[4] = {av.x, av.y, av.z, av.w};
            float bb[4] = {bv.x, bv.y, bv.z, bv.w};
#pragma unroll
            for (int i = 0; i < 4; i++)
#pragma unroll
                for (int j = 0; j < 4; j++) a4[i * 4 + j] += aa[i] * bb[j];
        }
#pragma unroll
        for (int ai = 0; ai < 4; ai++)
#pragma unroll
            for (int bi = 0; bi < 4; bi++) {
                int i = 4 * ti + ai, j = 4 * tj + bi;
                if (i <= j && j < 27) {
                    int flat = 27 * i - (i * (i - 1)) / 2 + (j - i);
                    uint16_t h, l;
                    f2hilo(a4[ai * 4 + bi], h, l);
                    Ohi[s * 512 + 128 + flat] = h;
                    Olo[s * 512 + 128 + flat] = l;
                }
            }
    } else if (lane == 28) {
        for (int c = 506; c < 512; c++) { Ohi[s * 512 + c] = 0; Olo[s * 512 + c] = 0; }
    }
}

// ---------------- final 256 -> 1 dot ----------------
__global__ void final_dot_kernel(const uint16_t* __restrict__ Ahi, const uint16_t* __restrict__ Alo,
                                 const float* __restrict__ w, const float* __restrict__ b,
                                 float* __restrict__ out) {
    const int warp = threadIdx.x >> 5;
    const int lane = threadIdx.x & 31;
    const size_t s = (size_t)blockIdx.x * 8 + warp;
    uint4 h4 = *(const uint4*)&Ahi[s * 256 + lane * 8];
    uint4 l4 = *(const uint4*)&Alo[s * 256 + lane * 8];
    uint32_t hw[4] = {h4.x, h4.y, h4.z, h4.w};
    uint32_t lw[4] = {l4.x, l4.y, l4.z, l4.w};
    float acc = 0.f;
#pragma unroll
    for (int q = 0; q < 4; q++) {
        float v0 = b2f((uint16_t)(hw[q] & 0xFFFF)) + b2f((uint16_t)(lw[q] & 0xFFFF));
        float v1 = b2f((uint16_t)(hw[q] >> 16))    + b2f((uint16_t)(lw[q] >> 16));
        acc += v0 * w[lane * 8 + q * 2];
        acc += v1 * w[lane * 8 + q * 2 + 1];
    }
#pragma unroll
    for (int o = 16; o; o >>= 1) acc += __shfl_xor_sync(0xFFFFFFFFu, acc, o);
    if (lane == 0) out[s] = acc + b[0];
}

// ---------------- host launch ----------------
extern "C" void kernel_launch(void* const* d_in, const int* in_sizes, int n_in,
                              void* d_out, int out_size) {
    const float* dense = (const float*)d_in[0];
    const int*   sidx  = (const int*)d_in[1];
    const float* emb   = (const float*)d_in[2];
    const float* bw0 = (const float*)d_in[3];  const float* bb0 = (const float*)d_in[4];
    const float* bw1 = (const float*)d_in[5];  const float* bb1 = (const float*)d_in[6];
    const float* bw2 = (const float*)d_in[7];  const float* bb2 = (const float*)d_in[8];
    const float* tw0 = (const float*)d_in[9];  const float* tb0 = (const float*)d_in[10];
    const float* tw1 = (const float*)d_in[11]; const float* tb1 = (const float*)d_in[12];
    const float* tw2 = (const float*)d_in[13]; const float* tb2 = (const float*)d_in[14];
    const float* tw3 = (const float*)d_in[15]; const float* tb3 = (const float*)d_in[16];
    const float* tw4 = (const float*)d_in[17]; const float* tb4 = (const float*)d_in[18];

    uint16_t *bufAh, *bufAl, *bufBh, *bufBl, *wth, *wtl;
    cudaGetSymbolAddress((void**)&bufAh, g_bufA_hi);
    cudaGetSymbolAddress((void**)&bufAl, g_bufA_lo);
    cudaGetSymbolAddress((void**)&bufBh, g_bufB_hi);
    cudaGetSymbolAddress((void**)&bufBl, g_bufB_lo);
    cudaGetSymbolAddress((void**)&wth, g_wt_hi);
    cudaGetSymbolAddress((void**)&wtl, g_wt_lo);

    const int DSM = 3 * STAGE_B;   // 98304
    cudaFuncSetAttribute(gemm_hmma, cudaFuncAttributeMaxDynamicSharedMemorySize, DSM);
    cudaFuncSetAttribute(interact_kernel, cudaFuncAttributeMaxDynamicSharedMemorySize, 114688);

    dim3 blk(256);

    // conversions (hi/lo split, weights transposed + K-padded)
    conv_dense_kernel<<<BATCH * 32 / 256, blk>>>(dense, bufAh, bufAl);
    conv_wt_kernel<<<(512 * 32 + 255) / 256, blk>>>(bw0, wth + 0,       wtl + 0,       13,   512, 32);
    conv_wt_kernel<<<(256 * 512 + 255) / 256, blk>>>(bw1, wth + 16384,  wtl + 16384,   512,  256, 512);
    conv_wt_kernel<<<(128 * 256 + 255) / 256, blk>>>(bw2, wth + 147456, wtl + 147456,  256,  128, 256);
    conv_wt_kernel<<<(1024 * 512 + 255) / 256, blk>>>(tw0, wth + 180224, wtl + 180224, 506, 1024, 512);
    conv_wt_kernel<<<(1024 * 1024 + 255) / 256, blk>>>(tw1, wth + 704512, wtl + 704512, 1024, 1024, 1024);
    conv_wt_kernel<<<(512 * 1024 + 255) / 256, blk>>>(tw2, wth + 1753088, wtl + 1753088, 1024, 512, 1024);
    conv_wt_kernel<<<(256 * 512 + 255) / 256, blk>>>(tw3, wth + 2277376, wtl + 2277376, 512, 256, 512);

    // bottom MLP
    gemm_hmma<<<dim3(4, 512), blk, DSM>>>(bufAh, bufAl, wth + 0,      wtl + 0,      bb0, bufBh, bufBl, 512, 32, 1);
    gemm_hmma<<<dim3(2, 512), blk, DSM>>>(bufBh, bufBl, wth + 16384,  wtl + 16384,  bb1, bufAh, bufAl, 256, 512, 1);
    gemm_hmma<<<dim3(1, 512), blk, DSM>>>(bufAh, bufAl, wth + 147456, wtl + 147456, bb2, bufBh, bufBl, 128, 256, 1);

    // gather + interaction -> [B, 512] (506 used, zero-padded)
    interact_kernel<<<BATCH / 8, blk, 114688>>>(bufBh, bufBl, emb, sidx, bufAh, bufAl);

    // top MLP
    gemm_hmma<<<dim3(8, 512), blk, DSM>>>(bufAh, bufAl, wth + 180224,  wtl + 180224,  tb0, bufBh, bufBl, 1024, 512, 1);
    gemm_hmma<<<dim3(8, 512), blk, DSM>>>(bufBh, bufBl, wth + 704512,  wtl + 704512,  tb1, bufAh, bufAl, 1024, 1024, 1);
    gemm_hmma<<<dim3(4, 512), blk, DSM>>>(bufAh, bufAl, wth + 1753088, wtl + 1753088, tb2, bufBh, bufBl, 512, 1024, 1);
    gemm_hmma<<<dim3(2, 512), blk, DSM>>>(bufBh, bufBl, wth + 2277376, wtl + 2277376, tb3, bufAh, bufAl, 256, 512, 1);

    // final 256 -> 1
    final_dot_kernel<<<BATCH / 8, blk>>>(bufAh, bufAl, tw4, tb4, (float*)d_out);
}

// round 6
// speedup vs baseline: 1.1940x; 1.0005x over previous
#include <cuda_runtime.h>
#include <cuda_bf16.h>
#include <stdint.h>

#define BATCH 65536
#define VOCAB 1048576

// ---------------- device scratch (no allocation allowed) ----------------
__device__ uint16_t g_bufA_hi[BATCH * 1024];
__device__ uint16_t g_bufA_lo[BATCH * 1024];
__device__ uint16_t g_bufB_hi[BATCH * 1024];
__device__ uint16_t g_bufB_lo[BATCH * 1024];
__device__ uint16_t g_wt_hi[2408448];
__device__ uint16_t g_wt_lo[2408448];

// weight offsets (transposed [N,K], K padded to mult of 32):
// bw0 -> [512 ,  32] off 0
// bw1 -> [256 , 512] off 16384
// bw2 -> [128 , 256] off 147456
// tw0 -> [1024, 512] off 180224
// tw1 -> [1024,1024] off 704512
// tw2 -> [512 ,1024] off 1753088
// tw3 -> [256 , 512] off 2277376     total 2408448

__device__ __forceinline__ void f2hilo(float x, uint16_t &hi, uint16_t &lo) {
    __nv_bfloat16 h = __float2bfloat16(x);
    float hf = __bfloat162float(h);
    __nv_bfloat16 l = __float2bfloat16(x - hf);
    hi = __bfloat16_as_ushort(h);
    lo = __bfloat16_as_ushort(l);
}
__device__ __forceinline__ float b2f(uint16_t u) {
    return __bfloat162float(__ushort_as_bfloat16(u));
}

// ---------------- PTX helpers ----------------
__device__ __forceinline__ uint32_t smem_u32(const void* p) {
    return (uint32_t)__cvta_generic_to_shared(p);
}
__device__ __forceinline__ void cp16(uint32_t s, const void* g) {
    asm volatile("cp.async.cg.shared.global [%0], [%1], 16;\n" :: "r"(s), "l"(g));
}
#define CP_COMMIT() asm volatile("cp.async.commit_group;\n" ::: "memory")
#define CP_WAIT2()  asm volatile("cp.async.wait_group 2;\n" ::: "memory")

__device__ __forceinline__ void mma_bf16(float* c, const uint32_t* a, const uint32_t* b) {
    asm volatile(
        "mma.sync.aligned.m16n8k16.row.col.f32.bf16.bf16.f32 "
        "{%0,%1,%2,%3}, {%4,%5,%6,%7}, {%8,%9}, {%0,%1,%2,%3};\n"
        : "+f"(c[0]), "+f"(c[1]), "+f"(c[2]), "+f"(c[3])
        : "r"(a[0]), "r"(a[1]), "r"(a[2]), "r"(a[3]), "r"(b[0]), "r"(b[1]));
}
__device__ __forceinline__ void ldsm4(uint32_t* r, uint32_t addr) {
    asm volatile("ldmatrix.sync.aligned.m8n8.x4.shared.b16 {%0,%1,%2,%3}, [%4];\n"
                 : "=r"(r[0]), "=r"(r[1]), "=r"(r[2]), "=r"(r[3])
                 : "r"(addr));
}
// SW64 swizzle for 64-byte rows (conflict-free ldmatrix, 16B-aligned cp.async)
__device__ __forceinline__ uint32_t swz(uint32_t off) {
    return off ^ ((off >> 3) & 0x30);
}

// ---------------- conversion kernels ----------------
__global__ void conv_dense_kernel(const float* __restrict__ d,
                                  uint16_t* __restrict__ hi, uint16_t* __restrict__ lo) {
    int idx = blockIdx.x * blockDim.x + threadIdx.x;   // BATCH*32
    int b = idx >> 5, k = idx & 31;
    float v = (k < 13) ? d[b * 13 + k] : 0.f;
    uint16_t h, l;
    f2hilo(v, h, l);
    hi[idx] = h; lo[idx] = l;
}

__global__ void conv_wt_kernel(const float* __restrict__ W,
                               uint16_t* __restrict__ hi, uint16_t* __restrict__ lo,
                               int K, int N, int Kpad) {
    int idx = blockIdx.x * blockDim.x + threadIdx.x;
    if (idx >= N * Kpad) return;
    int n = idx / Kpad, k = idx % Kpad;
    float v = (k < K) ? W[(size_t)k * N + n] : 0.f;
    uint16_t h, l;
    f2hilo(v, h, l);
    hi[idx] = h; lo[idx] = l;
}

// ---------------- bf16x3 GEMM (HMMA, cp.async 3-stage): O = act(A @ W^T + b) ----
// A: [BATCH, K] hi/lo row-major. W: [N, K] hi/lo row-major.
// Block tile 128x128, BK=32, 8 warps (4m x 2n), warp tile 32x64. 2 CTAs/SM.
#define STAGE_B 32768          // Ah 8K | Al 8K | Bh 8K | Bl 8K
#define OFF_AL  8192
#define OFF_BH  16384
#define OFF_BL  24576

__global__ __launch_bounds__(256, 2)
void gemm_hmma(const uint16_t* __restrict__ Ahi, const uint16_t* __restrict__ Alo,
               const uint16_t* __restrict__ Whi, const uint16_t* __restrict__ Wlo,
               const float* __restrict__ bias,
               uint16_t* __restrict__ Ohi, uint16_t* __restrict__ Olo,
               int Nsz, int K, int relu) {
    extern __shared__ __align__(16) uint8_t dsm[];
    const uint32_t sbase = smem_u32(dsm);

    const int tid  = threadIdx.x;
    const int lane = tid & 31;
    const int warp = tid >> 5;
    const int wm = warp & 3;
    const int wn = warp >> 2;
    const size_t mBase = (size_t)blockIdx.y * 128;
    const int    nBase = blockIdx.x * 128;
    const int    nch   = K >> 5;

    // each thread issues 8 cp.async per chunk: 4 A-half, 4 B-half
    // i in [0,2048): half=i>>10, buf=(i>>9)&1, r=(i>>2)&127, ch=i&3
    auto issue = [&](int c) {
        const uint32_t st = sbase + (c % 3) * STAGE_B;
        const int k0 = c << 5;
#pragma unroll
        for (int q = 0; q < 8; q++) {
            int i = q * 256 + tid;
            int half = i >> 10, buf = (i >> 9) & 1, r = (i >> 2) & 127, ch = i & 3;
            const uint16_t* g;
            uint32_t s;
            if (half == 0) {
                g = (buf ? Alo : Ahi) + (mBase + r) * (size_t)K + k0 + ch * 8;
                s = st + buf * OFF_AL + swz(r * 64 + ch * 16);
            } else {
                g = (buf ? Wlo : Whi) + (size_t)(nBase + r) * K + k0 + ch * 8;
                s = st + OFF_BH + buf * 8192 + swz(r * 64 + ch * 16);
            }
            cp16(s, g);
        }
    };

    float acc[2][8][4];
#pragma unroll
    for (int a = 0; a < 2; a++)
#pragma unroll
        for (int b = 0; b < 8; b++)
#pragma unroll
            for (int c = 0; c < 4; c++) acc[a][b][c] = 0.f;

    issue(0); CP_COMMIT();
    if (nch > 1) issue(1);
    CP_COMMIT();

    for (int c = 0; c < nch; c++) {
        __syncthreads();                 // all warps done with chunk c-1
        if (c + 2 < nch) issue(c + 2);
        CP_COMMIT();
        CP_WAIT2();                      // chunk c landed (for this thread)
        __syncthreads();                 // ...for all threads

        const uint32_t st = sbase + (c % 3) * STAGE_B;
#pragma unroll
        for (int kk = 0; kk < 2; kk++) {
            // A fragments: 32 rows x k16, hi+lo
            uint32_t aH[2][4], aL[2][4];
#pragma unroll
            for (int mt = 0; mt < 2; mt++) {
                uint32_t off = (uint32_t)(wm * 32 + mt * 16 + (lane & 15)) * 64
                             + kk * 32 + (lane >> 4) * 16;
                ldsm4(aH[mt], st + swz(off));
                ldsm4(aL[mt], st + OFF_AL + swz(off));
            }
#pragma unroll
            for (int np = 0; np < 4; np++) {
                uint32_t off = (uint32_t)(wn * 64 + np * 16 + (lane & 7) + ((lane >> 4) << 3)) * 64
                             + kk * 32 + (((lane >> 3) & 1) << 4);
                uint32_t bt[4];
                ldsm4(bt, st + OFF_BH + swz(off));      // B hi
#pragma unroll
                for (int mt = 0; mt < 2; mt++) {
                    mma_bf16(acc[mt][np * 2],     aH[mt], bt);
                    mma_bf16(acc[mt][np * 2 + 1], aH[mt], bt + 2);
                    mma_bf16(acc[mt][np * 2],     aL[mt], bt);
                    mma_bf16(acc[mt][np * 2 + 1], aL[mt], bt + 2);
                }
                ldsm4(bt, st + OFF_BL + swz(off));      // B lo
#pragma unroll
                for (int mt = 0; mt < 2; mt++) {
                    mma_bf16(acc[mt][np * 2],     aH[mt], bt);
                    mma_bf16(acc[mt][np * 2 + 1], aH[mt], bt + 2);
                }
            }
        }
    }

    // epilogue: bias + relu + hi/lo split + store
#pragma unroll
    for (int mt = 0; mt < 2; mt++) {
        size_t m0 = mBase + wm * 32 + mt * 16 + (lane >> 2);
#pragma unroll
        for (int nt = 0; nt < 8; nt++) {
            int n = nBase + wn * 64 + nt * 8 + (lane & 3) * 2;
            float b0 = bias[n], b1 = bias[n + 1];
            float v0 = acc[mt][nt][0] + b0;
            float v1 = acc[mt][nt][1] + b1;
            float v2 = acc[mt][nt][2] + b0;
            float v3 = acc[mt][nt][3] + b1;
            if (relu) {
                v0 = fmaxf(v0, 0.f); v1 = fmaxf(v1, 0.f);
                v2 = fmaxf(v2, 0.f); v3 = fmaxf(v3, 0.f);
            }
            uint16_t h0, l0, h1, l1;
            f2hilo(v0, h0, l0); f2hilo(v1, h1, l1);
            *(uint32_t*)&Ohi[m0 * Nsz + n] = (uint32_t)h0 | ((uint32_t)h1 << 16);
            *(uint32_t*)&Olo[m0 * Nsz + n] = (uint32_t)l0 | ((uint32_t)l1 << 16);
            f2hilo(v2, h0, l0); f2hilo(v3, h1, l1);
            *(uint32_t*)&Ohi[(m0 + 8) * Nsz + n] = (uint32_t)h0 | ((uint32_t)h1 << 16);
            *(uint32_t*)&Olo[(m0 + 8) * Nsz + n] = (uint32_t)l0 | ((uint32_t)l1 << 16);
        }
    }
}

// ---------------- embedding gather + pairwise interaction ----------------
__global__ __launch_bounds__(256, 1)
void interact_kernel(const uint16_t* __restrict__ Hhi, const uint16_t* __restrict__ Hlo,
                     const float* __restrict__ emb, const int* __restrict__ sidx,
                     uint16_t* __restrict__ Ohi, uint16_t* __restrict__ Olo) {
    extern __shared__ float comb[];                 // 8 * 128 * 28 floats
    const int warp = threadIdx.x >> 5;
    const int lane = threadIdx.x & 31;
    const size_t s = (size_t)blockIdx.x * 8 + warp;
    float* C = comb + warp * (128 * 28);

    {
        uint2 hh = *(const uint2*)&Hhi[s * 128 + lane * 4];
        uint2 ll = *(const uint2*)&Hlo[s * 128 + lane * 4];
        uint16_t hu[4] = {(uint16_t)(hh.x & 0xFFFF), (uint16_t)(hh.x >> 16),
                          (uint16_t)(hh.y & 0xFFFF), (uint16_t)(hh.y >> 16)};
        uint16_t lu[4] = {(uint16_t)(ll.x & 0xFFFF), (uint16_t)(ll.x >> 16),
                          (uint16_t)(ll.y & 0xFFFF), (uint16_t)(ll.y >> 16)};
#pragma unroll
        for (int j = 0; j < 4; j++) {
            float v = b2f(hu[j]) + b2f(lu[j]);
            C[(4 * lane + j) * 28 + 0] = v;
            C[(4 * lane + j) * 28 + 27] = 0.f;
        }
        *(uint2*)&Ohi[s * 512 + lane * 4] = hh;
        *(uint2*)&Olo[s * 512 + lane * 4] = ll;
    }

    for (int v = 0; v < 26; v++) {
        int id = sidx[s * 26 + v] & (VOCAB - 1);
        float4 e = *(const float4*)&emb[(size_t)id * 128 + lane * 4];
        C[(4 * lane + 0) * 28 + (v + 1)] = e.x;
        C[(4 * lane + 1) * 28 + (v + 1)] = e.y;
        C[(4 * lane + 2) * 28 + (v + 1)] = e.z;
        C[(4 * lane + 3) * 28 + (v + 1)] = e.w;
    }
    __syncwarp();

    if (lane < 28) {
        int rem = lane, ti = 0;
        while (rem >= 7 - ti) { rem -= 7 - ti; ti++; }
        int tj = ti + rem;

        float a4[16];
#pragma unroll
        for (int i = 0; i < 16; i++) a4[i] = 0.f;

        const float* Ca = C + 4 * ti;
        const float* Cb = C + 4 * tj;
#pragma unroll 4
        for (int k = 0; k < 128; k++) {
            float4 av = *(const float4*)(Ca + k * 28);
            float4 bv = *(const float4*)(Cb + k * 28);
            float aa[4] = {av.x, av.y, av.z, av.w};
            float bb[4] = {bv.x, bv.y, bv.z, bv.w};
#pragma unroll
            for (int i = 0; i < 4; i++)
#pragma unroll
                for (int j = 0; j < 4; j++) a4[i * 4 + j] += aa[i] * bb[j];
        }
#pragma unroll
        for (int ai = 0; ai < 4; ai++)
#pragma unroll
            for (int bi = 0; bi < 4; bi++) {
                int i = 4 * ti + ai, j = 4 * tj + bi;
                if (i <= j && j < 27) {
                    int flat = 27 * i - (i * (i - 1)) / 2 + (j - i);
                    uint16_t h, l;
                    f2hilo(a4[ai * 4 + bi], h, l);
                    Ohi[s * 512 + 128 + flat] = h;
                    Olo[s * 512 + 128 + flat] = l;
                }
            }
    } else if (lane == 28) {
        for (int c = 506; c < 512; c++) { Ohi[s * 512 + c] = 0; Olo[s * 512 + c] = 0; }
    }
}

// ---------------- final 256 -> 1 dot ----------------
__global__ void final_dot_kernel(const uint16_t* __restrict__ Ahi, const uint16_t* __restrict__ Alo,
                                 const float* __restrict__ w, const float* __restrict__ b,
                                 float* __restrict__ out) {
    const int warp = threadIdx.x >> 5;
    const int lane = threadIdx.x & 31;
    const size_t s = (size_t)blockIdx.x * 8 + warp;
    uint4 h4 = *(const uint4*)&Ahi[s * 256 + lane * 8];
    uint4 l4 = *(const uint4*)&Alo[s * 256 + lane * 8];
    uint32_t hw[4] = {h4.x, h4.y, h4.z, h4.w};
    uint32_t lw[4] = {l4.x, l4.y, l4.z, l4.w};
    float acc = 0.f;
#pragma unroll
    for (int q = 0; q < 4; q++) {
        float v0 = b2f((uint16_t)(hw[q] & 0xFFFF)) + b2f((uint16_t)(lw[q] & 0xFFFF));
        float v1 = b2f((uint16_t)(hw[q] >> 16))    + b2f((uint16_t)(lw[q] >> 16));
        acc += v0 * w[lane * 8 + q * 2];
        acc += v1 * w[lane * 8 + q * 2 + 1];
    }
#pragma unroll
    for (int o = 16; o; o >>= 1) acc += __shfl_xor_sync(0xFFFFFFFFu, acc, o);
    if (lane == 0) out[s] = acc + b[0];
}

// ---------------- host launch ----------------
extern "C" void kernel_launch(void* const* d_in, const int* in_sizes, int n_in,
                              void* d_out, int out_size) {
    const float* dense = (const float*)d_in[0];
    const int*   sidx  = (const int*)d_in[1];
    const float* emb   = (const float*)d_in[2];
    const float* bw0 = (const float*)d_in[3];  const float* bb0 = (const float*)d_in[4];
    const float* bw1 = (const float*)d_in[5];  const float* bb1 = (const float*)d_in[6];
    const float* bw2 = (const float*)d_in[7];  const float* bb2 = (const float*)d_in[8];
    const float* tw0 = (const float*)d_in[9];  const float* tb0 = (const float*)d_in[10];
    const float* tw1 = (const float*)d_in[11]; const float* tb1 = (const float*)d_in[12];
    const float* tw2 = (const float*)d_in[13]; const float* tb2 = (const float*)d_in[14];
    const float* tw3 = (const float*)d_in[15]; const float* tb3 = (const float*)d_in[16];
    const float* tw4 = (const float*)d_in[17]; const float* tb4 = (const float*)d_in[18];

    uint16_t *bufAh, *bufAl, *bufBh, *bufBl, *wth, *wtl;
    cudaGetSymbolAddress((void**)&bufAh, g_bufA_hi);
    cudaGetSymbolAddress((void**)&bufAl, g_bufA_lo);
    cudaGetSymbolAddress((void**)&bufBh, g_bufB_hi);
    cudaGetSymbolAddress((void**)&bufBl, g_bufB_lo);
    cudaGetSymbolAddress((void**)&wth, g_wt_hi);
    cudaGetSymbolAddress((void**)&wtl, g_wt_lo);

    const int DSM = 3 * STAGE_B;   // 98304
    cudaFuncSetAttribute(gemm_hmma, cudaFuncAttributeMaxDynamicSharedMemorySize, DSM);
    cudaFuncSetAttribute(interact_kernel, cudaFuncAttributeMaxDynamicSharedMemorySize, 114688);

    dim3 blk(256);

    // conversions (hi/lo split, weights transposed + K-padded)
    conv_dense_kernel<<<BATCH * 32 / 256, blk>>>(dense, bufAh, bufAl);
    conv_wt_kernel<<<(512 * 32 + 255) / 256, blk>>>(bw0, wth + 0,       wtl + 0,       13,   512, 32);
    conv_wt_kernel<<<(256 * 512 + 255) / 256, blk>>>(bw1, wth + 16384,  wtl + 16384,   512,  256, 512);
    conv_wt_kernel<<<(128 * 256 + 255) / 256, blk>>>(bw2, wth + 147456, wtl + 147456,  256,  128, 256);
    conv_wt_kernel<<<(1024 * 512 + 255) / 256, blk>>>(tw0, wth + 180224, wtl + 180224, 506, 1024, 512);
    conv_wt_kernel<<<(1024 * 1024 + 255) / 256, blk>>>(tw1, wth + 704512, wtl + 704512, 1024, 1024, 1024);
    conv_wt_kernel<<<(512 * 1024 + 255) / 256, blk>>>(tw2, wth + 1753088, wtl + 1753088, 1024, 512, 1024);
    conv_wt_kernel<<<(256 * 512 + 255) / 256, blk>>>(tw3, wth + 2277376, wtl + 2277376, 512, 256, 512);

    // bottom MLP
    gemm_hmma<<<dim3(4, 512), blk, DSM>>>(bufAh, bufAl, wth + 0,      wtl + 0,      bb0, bufBh, bufBl, 512, 32, 1);
    gemm_hmma<<<dim3(2, 512), blk, DSM>>>(bufBh, bufBl, wth + 16384,  wtl + 16384,  bb1, bufAh, bufAl, 256, 512, 1);
    gemm_hmma<<<dim3(1, 512), blk, DSM>>>(bufAh, bufAl, wth + 147456, wtl + 147456, bb2, bufBh, bufBl, 128, 256, 1);

    // gather + interaction -> [B, 512] (506 used, zero-padded)
    interact_kernel<<<BATCH / 8, blk, 114688>>>(bufBh, bufBl, emb, sidx, bufAh, bufAl);

    // top MLP
    gemm_hmma<<<dim3(8, 512), blk, DSM>>>(bufAh, bufAl, wth + 180224,  wtl + 180224,  tb0, bufBh, bufBl, 1024, 512, 1);
    gemm_hmma<<<dim3(8, 512), blk, DSM>>>(bufBh, bufBl, wth + 704512,  wtl + 704512,  tb1, bufAh, bufAl, 1024, 1024, 1);
    gemm_hmma<<<dim3(4, 512), blk, DSM>>>(bufAh, bufAl, wth + 1753088, wtl + 1753088, tb2, bufBh, bufBl, 512, 1024, 1);
    gemm_hmma<<<dim3(2, 512), blk, DSM>>>(bufBh, bufBl, wth + 2277376, wtl + 2277376, tb3, bufAh, bufAl, 256, 512, 1);

    // final 256 -> 1
    final_dot_kernel<<<BATCH / 8, blk>>>(bufAh, bufAl, tw4, tb4, (float*)d_out);
}